// round 3
// baseline (speedup 1.0000x reference)
#include <cuda_runtime.h>
#include <cuda_bf16.h>
#include <cstdint>

// Per-row mode of x[N, 64], values guaranteed integer in {0..7}.
// Strategy:
//   - packed histogram: 8 counters x 8 bits in one uint64 (max count 64 < 256)
//   - 16 lanes per row, each lane loads ONE float4 (fully coalesced 512B/warp)
//   - 4 rows per warp (2 independent float4 loads/lane -> MLP=2)
//   - merge histograms with 4x __shfl_xor on the 64-bit pack
//   - mode = smallest value among max counts (strict > scan from v=0)

__global__ void __launch_bounds__(256) mode_rows_kernel(
    const float4* __restrict__ xv,   // x reinterpreted as float4 (16 per row)
    float* __restrict__ out,
    long long n_rows)
{
    const long long warpId = ((long long)blockIdx.x * blockDim.x + threadIdx.x) >> 5;
    const int lane = threadIdx.x & 31;

    const long long rowBase = warpId * 4;            // 4 rows per warp
    if (rowBase >= n_rows) return;

    // Row pair p covers rows rowBase+2p .. rowBase+2p+1 = 32 float4 = 32 lanes.
    // Lane l loads chunk (l & 15) of row (rowBase + 2p + (l >> 4)).
    const float4 a = xv[rowBase * 16 + lane];        // rows rowBase, rowBase+1
    const float4 b = xv[(rowBase + 2) * 16 + lane];  // rows rowBase+2, rowBase+3

    // Packed histograms: byte v holds count of value v.
    unsigned long long h0 = 0ull, h1 = 0ull;
    h0 += 1ull << ((((int)a.x) & 7) * 8);
    h0 += 1ull << ((((int)a.y) & 7) * 8);
    h0 += 1ull << ((((int)a.z) & 7) * 8);
    h0 += 1ull << ((((int)a.w) & 7) * 8);
    h1 += 1ull << ((((int)b.x) & 7) * 8);
    h1 += 1ull << ((((int)b.y) & 7) * 8);
    h1 += 1ull << ((((int)b.z) & 7) * 8);
    h1 += 1ull << ((((int)b.w) & 7) * 8);

    // Reduce across the 16 lanes of each half-warp (xor tree stays within half).
    #pragma unroll
    for (int m = 1; m <= 8; m <<= 1) {
        h0 += __shfl_xor_sync(0xffffffffu, h0, m);
        h1 += __shfl_xor_sync(0xffffffffu, h1, m);
    }

    // Lanes 0 and 16 hold full histograms for their rows.
    if ((lane & 15) == 0) {
        const long long row = rowBase + (lane >> 4);

        // mode from h0 -> out[row]
        {
            int bestV = 0;
            int bestC = (int)(h0 & 0xffull);
            #pragma unroll
            for (int v = 1; v < 8; v++) {
                int c = (int)((h0 >> (8 * v)) & 0xffull);
                if (c > bestC) { bestC = c; bestV = v; }   // strict >: smallest value wins ties
            }
            out[row] = (float)bestV;
        }
        // mode from h1 -> out[row + 2]
        if (row + 2 < n_rows) {
            int bestV = 0;
            int bestC = (int)(h1 & 0xffull);
            #pragma unroll
            for (int v = 1; v < 8; v++) {
                int c = (int)((h1 >> (8 * v)) & 0xffull);
                if (c > bestC) { bestC = c; bestV = v; }
            }
            out[row + 2] = (float)bestV;
        }
    }
}

extern "C" void kernel_launch(void* const* d_in, const int* in_sizes, int n_in,
                              void* d_out, int out_size)
{
    const float* x = (const float*)d_in[0];
    float* out = (float*)d_out;

    const long long n_elems = (long long)in_sizes[0];
    const long long n_rows = n_elems / 64;           // K = 64

    // 4 rows per warp, 8 warps per block -> 32 rows per block.
    const long long n_warps = (n_rows + 3) / 4;
    const int threads = 256;
    const long long blocks = (n_warps * 32 + threads - 1) / threads;

    mode_rows_kernel<<<(unsigned)blocks, threads>>>(
        (const float4*)x, out, n_rows);
}

// round 4
// speedup vs baseline: 1.5972x; 1.5972x over previous
#include <cuda_runtime.h>
#include <cuda_bf16.h>
#include <cstdint>

// Per-row mode of x[N, 64], values guaranteed integer in {0..7}.
//
// ALU-lean design (R2 was alu-pipe bound at 75%):
//  - lane layout: warp = 8 rows (2 iterations of 4). Within an iteration,
//    lane l -> row (l>>3), chunks (l&7) and (l&7)+8  => 8 elements/lane,
//    ONE 32-bit nibble histogram per lane (max count 8 <= 15).
//  - per-element update: FFMA magic (x*4 + 2^23 -> mantissa low bits = 4v),
//    then h += 1 << (bits & 0x1C): 1 FFMA + LOP3 + SHF + IADD3.
//  - widen nibbles->bytes once (even/odd value words), 3-level shfl_xor
//    reduce over the 8 lanes of each row (byte counts <= 64).
//  - distributed mode: lane j in [0,8) owns value j, key=(cnt<<3)|(7-j),
//    3-level max-reduce => highest count, smallest value on ties.

__device__ __forceinline__ unsigned acc_nib(unsigned h, float x) {
    // bits of (x*4 + 2^23) has 4*x in its low mantissa bits (x in {0..7} exact)
    unsigned b = __float_as_uint(fmaf(x, 4.0f, 8388608.0f));
    return h + (1u << (b & 0x1Cu));
}

__global__ void __launch_bounds__(256) mode_rows_kernel(
    const float4* __restrict__ xv,   // x as float4 (16 per row)
    float* __restrict__ out,
    int n_rows)
{
    const int warpId = (int)(((unsigned)blockIdx.x * blockDim.x + threadIdx.x) >> 5);
    const int lane = threadIdx.x & 31;
    const int rowBase = warpId * 8;
    if (rowBase >= n_rows) return;

    if (rowBase + 8 <= n_rows) {
        const int sub = lane >> 3;          // row within 4-row group
        const int c   = lane & 7;           // chunk index 0..7
        const bool useOdd = (c & 1) != 0;   // value parity this lane owns
        const int  byteSh = (c >> 1) * 8;   // byte position of owned value
        const int  tie    = 7 - c;          // tie-break: smaller value wins

        // iteration 0: rows rowBase..rowBase+3 ; iteration 1: +4
        const float4* p0 = xv + (size_t)(rowBase + sub) * 16 + c;
        const float4* p1 = p0 + 4 * 16;

        // hoist all 4 loads (coalesced: 8 lanes x 16B = one 128B line)
        const float4 a0 = p0[0];
        const float4 b0 = p0[8];
        const float4 a1 = p1[0];
        const float4 b1 = p1[8];

        // two independent accumulation chains per hist for ILP
        unsigned hA0 = 0, hB0 = 0, hA1 = 0, hB1 = 0;
        hA0 = acc_nib(hA0, a0.x); hB0 = acc_nib(hB0, b0.x);
        hA0 = acc_nib(hA0, a0.y); hB0 = acc_nib(hB0, b0.y);
        hA0 = acc_nib(hA0, a0.z); hB0 = acc_nib(hB0, b0.z);
        hA0 = acc_nib(hA0, a0.w); hB0 = acc_nib(hB0, b0.w);
        hA1 = acc_nib(hA1, a1.x); hB1 = acc_nib(hB1, b1.x);
        hA1 = acc_nib(hA1, a1.y); hB1 = acc_nib(hB1, b1.y);
        hA1 = acc_nib(hA1, a1.z); hB1 = acc_nib(hB1, b1.z);
        hA1 = acc_nib(hA1, a1.w); hB1 = acc_nib(hB1, b1.w);
        const unsigned h0 = hA0 + hB0;      // nibble v = count of value v (<=8)
        const unsigned h1 = hA1 + hB1;

        // widen nibbles -> bytes: even word = values {0,2,4,6}, odd = {1,3,5,7}
        unsigned e0 = h0 & 0x0F0F0F0Fu, o0 = (h0 >> 4) & 0x0F0F0F0Fu;
        unsigned e1 = h1 & 0x0F0F0F0Fu, o1 = (h1 >> 4) & 0x0F0F0F0Fu;

        // reduce over the 8 lanes of each row (xor tree stays in 8-lane group)
        #pragma unroll
        for (int m = 1; m <= 4; m <<= 1) {
            e0 += __shfl_xor_sync(0xffffffffu, e0, m);
            o0 += __shfl_xor_sync(0xffffffffu, o0, m);
            e1 += __shfl_xor_sync(0xffffffffu, e1, m);
            o1 += __shfl_xor_sync(0xffffffffu, o1, m);
        }

        // distributed mode: lane j owns value j (byte j>>1 of word j&1)
        const unsigned w0 = useOdd ? o0 : e0;
        const unsigned w1 = useOdd ? o1 : e1;
        int k0 = (int)(((w0 >> byteSh) & 0xFFu) << 3) | tie;
        int k1 = (int)(((w1 >> byteSh) & 0xFFu) << 3) | tie;
        #pragma unroll
        for (int m = 1; m <= 4; m <<= 1) {
            k0 = max(k0, __shfl_xor_sync(0xffffffffu, k0, m));
            k1 = max(k1, __shfl_xor_sync(0xffffffffu, k1, m));
        }

        if (c == 0) {
            out[rowBase + sub]     = (float)(7 - (k0 & 7));
            out[rowBase + 4 + sub] = (float)(7 - (k1 & 7));
        }
    } else {
        // tail (never taken for N % 8 == 0): one row per lane, scalar
        for (int r = rowBase + lane; r < n_rows; r += 32) {
            const float* rp = (const float*)xv + (size_t)r * 64;
            int cnt[8];
            #pragma unroll
            for (int v = 0; v < 8; v++) cnt[v] = 0;
            for (int i = 0; i < 64; i++) cnt[((int)rp[i]) & 7]++;
            int bestV = 0, bestC = cnt[0];
            #pragma unroll
            for (int v = 1; v < 8; v++)
                if (cnt[v] > bestC) { bestC = cnt[v]; bestV = v; }
            out[r] = (float)bestV;
        }
    }
}

extern "C" void kernel_launch(void* const* d_in, const int* in_sizes, int n_in,
                              void* d_out, int out_size)
{
    const float* x = (const float*)d_in[0];
    float* out = (float*)d_out;

    const long long n_elems = (long long)in_sizes[0];
    const int n_rows = (int)(n_elems / 64);   // K = 64

    // 8 rows per warp, 8 warps (256 threads) per block -> 64 rows per block
    const int threads = 256;
    const int blocks = (n_rows + 63) / 64;

    mode_rows_kernel<<<blocks, threads>>>((const float4*)x, out, n_rows);
}

// round 5
// speedup vs baseline: 1.5984x; 1.0007x over previous
#include <cuda_runtime.h>
#include <cuda_bf16.h>
#include <cstdint>

// Per-row mode of x[N, 64], values guaranteed integer in {0..7}.
//
// R4: memory-efficiency round (R3 was DRAM-bound at 84%).
//  - 16 rows per warp (4 groups of 4 rows), 8 hoisted float4 loads per lane
//    -> MLP=8, 128B in flight per thread.
//  - __ldcs streaming loads (stream-once data; keep L2 clean).
//  - per-element update: FFMA magic (x*4 + 2^23 -> 4v in low mantissa bits),
//    h += 1 << (bits & 0x1C) on a 32-bit nibble histogram (max count 8).
//  - widen nibbles->bytes, 3-level shfl_xor reduce over the 8 lanes of a row.
//  - distributed mode: lane j owns value j, key=(cnt<<3)|(7-j), max-reduce
//    -> highest count, smallest value on ties.

__device__ __forceinline__ unsigned acc_nib(unsigned h, float x) {
    unsigned b = __float_as_uint(fmaf(x, 4.0f, 8388608.0f));
    return h + (1u << (b & 0x1Cu));
}

__device__ __forceinline__ unsigned hist8(const float4& a, const float4& b) {
    // two independent chains for ILP, merged at the end
    unsigned hA = 0, hB = 0;
    hA = acc_nib(hA, a.x); hB = acc_nib(hB, b.x);
    hA = acc_nib(hA, a.y); hB = acc_nib(hB, b.y);
    hA = acc_nib(hA, a.z); hB = acc_nib(hB, b.z);
    hA = acc_nib(hA, a.w); hB = acc_nib(hB, b.w);
    return hA + hB;            // nibble v = count of value v among 8 elems
}

__global__ void __launch_bounds__(256) mode_rows_kernel(
    const float4* __restrict__ xv,   // x as float4 (16 per row)
    float* __restrict__ out,
    int n_rows)
{
    const int warpId = (int)(((unsigned)blockIdx.x * blockDim.x + threadIdx.x) >> 5);
    const int lane = threadIdx.x & 31;
    const int rowBase = warpId * 16;         // 16 rows per warp
    if (rowBase >= n_rows) return;

    if (rowBase + 16 <= n_rows) {
        const int sub = lane >> 3;           // row within each 4-row group
        const int c   = lane & 7;            // chunk index 0..7
        const bool useOdd = (c & 1) != 0;    // value parity this lane owns
        const int  byteSh = (c >> 1) * 8;    // byte position of owned value
        const int  tie    = 7 - c;           // tie-break: smaller value wins

        const float4* p = xv + (size_t)(rowBase + sub) * 16 + c;

        // hoist all 8 loads (each: 8 lanes x 16B = one 128B line), streaming
        const float4 a0 = __ldcs(p +   0);   // group 0, chunk c
        const float4 b0 = __ldcs(p +   8);   // group 0, chunk c+8
        const float4 a1 = __ldcs(p +  64);   // group 1 (+4 rows)
        const float4 b1 = __ldcs(p +  72);
        const float4 a2 = __ldcs(p + 128);   // group 2 (+8 rows)
        const float4 b2 = __ldcs(p + 136);
        const float4 a3 = __ldcs(p + 192);   // group 3 (+12 rows)
        const float4 b3 = __ldcs(p + 200);

        const unsigned h0 = hist8(a0, b0);
        const unsigned h1 = hist8(a1, b1);
        const unsigned h2 = hist8(a2, b2);
        const unsigned h3 = hist8(a3, b3);

        // widen nibbles -> bytes: even word = values {0,2,4,6}, odd = {1,3,5,7}
        unsigned e0 = h0 & 0x0F0F0F0Fu, o0 = (h0 >> 4) & 0x0F0F0F0Fu;
        unsigned e1 = h1 & 0x0F0F0F0Fu, o1 = (h1 >> 4) & 0x0F0F0F0Fu;
        unsigned e2 = h2 & 0x0F0F0F0Fu, o2 = (h2 >> 4) & 0x0F0F0F0Fu;
        unsigned e3 = h3 & 0x0F0F0F0Fu, o3 = (h3 >> 4) & 0x0F0F0F0Fu;

        // reduce over the 8 lanes of each row (xor tree stays in 8-lane group)
        #pragma unroll
        for (int m = 1; m <= 4; m <<= 1) {
            e0 += __shfl_xor_sync(0xffffffffu, e0, m);
            o0 += __shfl_xor_sync(0xffffffffu, o0, m);
            e1 += __shfl_xor_sync(0xffffffffu, e1, m);
            o1 += __shfl_xor_sync(0xffffffffu, o1, m);
            e2 += __shfl_xor_sync(0xffffffffu, e2, m);
            o2 += __shfl_xor_sync(0xffffffffu, o2, m);
            e3 += __shfl_xor_sync(0xffffffffu, e3, m);
            o3 += __shfl_xor_sync(0xffffffffu, o3, m);
        }

        // distributed mode: lane j owns value j (byte j>>1 of word j&1)
        const unsigned w0 = useOdd ? o0 : e0;
        const unsigned w1 = useOdd ? o1 : e1;
        const unsigned w2 = useOdd ? o2 : e2;
        const unsigned w3 = useOdd ? o3 : e3;
        int k0 = (int)(((w0 >> byteSh) & 0xFFu) << 3) | tie;
        int k1 = (int)(((w1 >> byteSh) & 0xFFu) << 3) | tie;
        int k2 = (int)(((w2 >> byteSh) & 0xFFu) << 3) | tie;
        int k3 = (int)(((w3 >> byteSh) & 0xFFu) << 3) | tie;
        #pragma unroll
        for (int m = 1; m <= 4; m <<= 1) {
            k0 = max(k0, __shfl_xor_sync(0xffffffffu, k0, m));
            k1 = max(k1, __shfl_xor_sync(0xffffffffu, k1, m));
            k2 = max(k2, __shfl_xor_sync(0xffffffffu, k2, m));
            k3 = max(k3, __shfl_xor_sync(0xffffffffu, k3, m));
        }

        if (c == 0) {
            out[rowBase +      sub] = (float)(7 - (k0 & 7));
            out[rowBase +  4 + sub] = (float)(7 - (k1 & 7));
            out[rowBase +  8 + sub] = (float)(7 - (k2 & 7));
            out[rowBase + 12 + sub] = (float)(7 - (k3 & 7));
        }
    } else {
        // tail (never taken for N % 16 == 0): one row per lane, scalar
        for (int r = rowBase + lane; r < n_rows; r += 32) {
            const float* rp = (const float*)xv + (size_t)r * 64;
            int cnt[8];
            #pragma unroll
            for (int v = 0; v < 8; v++) cnt[v] = 0;
            for (int i = 0; i < 64; i++) cnt[((int)rp[i]) & 7]++;
            int bestV = 0, bestC = cnt[0];
            #pragma unroll
            for (int v = 1; v < 8; v++)
                if (cnt[v] > bestC) { bestC = cnt[v]; bestV = v; }
            out[r] = (float)bestV;
        }
    }
}

extern "C" void kernel_launch(void* const* d_in, const int* in_sizes, int n_in,
                              void* d_out, int out_size)
{
    const float* x = (const float*)d_in[0];
    float* out = (float*)d_out;

    const long long n_elems = (long long)in_sizes[0];
    const int n_rows = (int)(n_elems / 64);   // K = 64

    // 16 rows per warp, 8 warps (256 threads) per block -> 128 rows per block
    const int threads = 256;
    const int blocks = (n_rows + 127) / 128;

    mode_rows_kernel<<<blocks, threads>>>((const float4*)x, out, n_rows);
}

// round 7
// speedup vs baseline: 1.6066x; 1.0051x over previous
#include <cuda_runtime.h>
#include <cuda_bf16.h>
#include <cstdint>

// Per-row mode of x[N, 64], values guaranteed integer in {0..7}.
//
// R6: R5's broken output-packing shuffle reverted to the verified R4 epilogue
// (shuffle returns the SOURCE lane's selected value — each source had picked
// its own group, not the destination's). Keep: default-cached loads (no
// __ldcs; R4 measured -1.6% DRAM util from evict-first) and 512-thr blocks.
//  - 16 rows per warp (4 groups of 4 rows), 8 hoisted float4 loads per lane.
//  - per-element update: FFMA magic (x*4 + 2^23 -> 4v in low mantissa bits),
//    h += 1 << (bits & 0x1C) on a 32-bit nibble histogram (max count 8).
//  - widen nibbles->bytes, 3-level shfl_xor reduce over the 8 lanes of a row.
//  - distributed mode: lane j owns value j, key=(cnt<<3)|(7-j), max-reduce
//    -> highest count, smallest value on ties.

__device__ __forceinline__ unsigned acc_nib(unsigned h, float x) {
    unsigned b = __float_as_uint(fmaf(x, 4.0f, 8388608.0f));
    return h + (1u << (b & 0x1Cu));
}

__device__ __forceinline__ unsigned hist8(const float4& a, const float4& b) {
    unsigned hA = 0, hB = 0;
    hA = acc_nib(hA, a.x); hB = acc_nib(hB, b.x);
    hA = acc_nib(hA, a.y); hB = acc_nib(hB, b.y);
    hA = acc_nib(hA, a.z); hB = acc_nib(hB, b.z);
    hA = acc_nib(hA, a.w); hB = acc_nib(hB, b.w);
    return hA + hB;            // nibble v = count of value v among 8 elems
}

__global__ void __launch_bounds__(512) mode_rows_kernel(
    const float4* __restrict__ xv,   // x as float4 (16 per row)
    float* __restrict__ out,
    int n_rows)
{
    const int warpId = (int)(((unsigned)blockIdx.x * blockDim.x + threadIdx.x) >> 5);
    const int lane = threadIdx.x & 31;
    const int rowBase = warpId * 16;         // 16 rows per warp
    if (rowBase >= n_rows) return;

    if (rowBase + 16 <= n_rows) {
        const int sub = lane >> 3;           // row within each 4-row group
        const int c   = lane & 7;            // chunk index 0..7
        const bool useOdd = (c & 1) != 0;    // value parity this lane owns
        const int  byteSh = (c >> 1) * 8;    // byte position of owned value
        const int  tie    = 7 - c;           // tie-break: smaller value wins

        const float4* p = xv + (size_t)(rowBase + sub) * 16 + c;

        // hoist all 8 loads (each: 8 lanes x 16B = one 128B line)
        const float4 a0 = p[  0];            // group 0, chunk c
        const float4 b0 = p[  8];            // group 0, chunk c+8
        const float4 a1 = p[ 64];            // group 1 (+4 rows)
        const float4 b1 = p[ 72];
        const float4 a2 = p[128];            // group 2 (+8 rows)
        const float4 b2 = p[136];
        const float4 a3 = p[192];            // group 3 (+12 rows)
        const float4 b3 = p[200];

        const unsigned h0 = hist8(a0, b0);
        const unsigned h1 = hist8(a1, b1);
        const unsigned h2 = hist8(a2, b2);
        const unsigned h3 = hist8(a3, b3);

        // widen nibbles -> bytes: even word = values {0,2,4,6}, odd = {1,3,5,7}
        unsigned e0 = h0 & 0x0F0F0F0Fu, o0 = (h0 >> 4) & 0x0F0F0F0Fu;
        unsigned e1 = h1 & 0x0F0F0F0Fu, o1 = (h1 >> 4) & 0x0F0F0F0Fu;
        unsigned e2 = h2 & 0x0F0F0F0Fu, o2 = (h2 >> 4) & 0x0F0F0F0Fu;
        unsigned e3 = h3 & 0x0F0F0F0Fu, o3 = (h3 >> 4) & 0x0F0F0F0Fu;

        // reduce over the 8 lanes of each row (xor tree stays in 8-lane group)
        #pragma unroll
        for (int m = 1; m <= 4; m <<= 1) {
            e0 += __shfl_xor_sync(0xffffffffu, e0, m);
            o0 += __shfl_xor_sync(0xffffffffu, o0, m);
            e1 += __shfl_xor_sync(0xffffffffu, e1, m);
            o1 += __shfl_xor_sync(0xffffffffu, o1, m);
            e2 += __shfl_xor_sync(0xffffffffu, e2, m);
            o2 += __shfl_xor_sync(0xffffffffu, o2, m);
            e3 += __shfl_xor_sync(0xffffffffu, e3, m);
            o3 += __shfl_xor_sync(0xffffffffu, o3, m);
        }

        // distributed mode: lane j owns value j (byte j>>1 of word j&1)
        const unsigned w0 = useOdd ? o0 : e0;
        const unsigned w1 = useOdd ? o1 : e1;
        const unsigned w2 = useOdd ? o2 : e2;
        const unsigned w3 = useOdd ? o3 : e3;
        int k0 = (int)(((w0 >> byteSh) & 0xFFu) << 3) | tie;
        int k1 = (int)(((w1 >> byteSh) & 0xFFu) << 3) | tie;
        int k2 = (int)(((w2 >> byteSh) & 0xFFu) << 3) | tie;
        int k3 = (int)(((w3 >> byteSh) & 0xFFu) << 3) | tie;
        #pragma unroll
        for (int m = 1; m <= 4; m <<= 1) {
            k0 = max(k0, __shfl_xor_sync(0xffffffffu, k0, m));
            k1 = max(k1, __shfl_xor_sync(0xffffffffu, k1, m));
            k2 = max(k2, __shfl_xor_sync(0xffffffffu, k2, m));
            k3 = max(k3, __shfl_xor_sync(0xffffffffu, k3, m));
        }

        // verified epilogue: lanes with c==0 (lanes 0,8,16,24) hold the final
        // keys for their sub-row in every group; 4 stores each.
        if (c == 0) {
            out[rowBase +      sub] = (float)(7 - (k0 & 7));
            out[rowBase +  4 + sub] = (float)(7 - (k1 & 7));
            out[rowBase +  8 + sub] = (float)(7 - (k2 & 7));
            out[rowBase + 12 + sub] = (float)(7 - (k3 & 7));
        }
    } else {
        // tail (never taken for N % 16 == 0): one row per lane, scalar
        for (int r = rowBase + lane; r < n_rows; r += 32) {
            const float* rp = (const float*)xv + (size_t)r * 64;
            int cnt[8];
            #pragma unroll
            for (int v = 0; v < 8; v++) cnt[v] = 0;
            for (int i = 0; i < 64; i++) cnt[((int)rp[i]) & 7]++;
            int bestV = 0, bestC = cnt[0];
            #pragma unroll
            for (int v = 1; v < 8; v++)
                if (cnt[v] > bestC) { bestC = cnt[v]; bestV = v; }
            out[r] = (float)bestV;
        }
    }
}

extern "C" void kernel_launch(void* const* d_in, const int* in_sizes, int n_in,
                              void* d_out, int out_size)
{
    const float* x = (const float*)d_in[0];
    float* out = (float*)d_out;

    const long long n_elems = (long long)in_sizes[0];
    const int n_rows = (int)(n_elems / 64);   // K = 64

    // 16 rows per warp, 16 warps (512 threads) per block -> 256 rows per block
    const int threads = 512;
    const int blocks = (n_rows + 255) / 256;

    mode_rows_kernel<<<blocks, threads>>>((const float4*)x, out, n_rows);
}